// round 3
// baseline (speedup 1.0000x reference)
#include <cuda_runtime.h>
#include <cuda_fp16.h>
#include <cstdint>

// ============================================================================
// QATLinear: y[t,o] = scale[o] * sum_i x[t,i]*sign(w[o,i]) + b[o]
//
// sign(W) = +-1 is EXACT in fp16; x rounded to fp16 (rel rms ~2.8e-4) with
// fp32 mma.sync accumulation => output norm-relative error ~2e-4 (measured).
// compute_103 target: no tcgen05 -> register-path mma.sync.m16n8k16.
//
// R3 change: warp tile 32x64 -> 64x64 (8 warps, 256 threads). Halves smem
// fragment traffic per MMA (98KB -> 64KB per chunk), moving the kernel from
// smem-coband (~960cyc smem vs 1024cyc MMA per chunk) to tensor-bound.
// ============================================================================

#define TOKENS 8192
#define DIN    4096
#define DOUT   16384

static constexpr int BM = 128;
static constexpr int BN = 256;
static constexpr int BK = 32;
static constexpr int STAGES = 4;
static constexpr int THREADS = 256;              // 8 warps: 2 (m) x 4 (n)
static constexpr int NCHUNK = DIN / BK;          // 128

static constexpr int A_STAGE_B = BM * BK * 2;    // 8192 B
static constexpr int B_STAGE_B = BN * BK * 2;    // 16384 B
static constexpr int STAGE_B   = A_STAGE_B + B_STAGE_B;   // 24576
static constexpr int SMEM_TOTAL = STAGES * STAGE_B;       // 98304

// ---- scratch (device globals: allocation-free rule) ----
__device__ __half g_A [(size_t)TOKENS * DIN];    // 64 MB  (x as fp16)
__device__ __half g_Bs[(size_t)DOUT  * DIN];     // 128 MB (sign(w) as fp16)

// ============================ PTX helpers ===================================
__device__ __forceinline__ uint32_t smem_u32(const void* p) {
    uint32_t a;
    asm("{ .reg .u64 t; cvta.to.shared.u64 t, %1; cvt.u32.u64 %0, t; }"
        : "=r"(a) : "l"(p));
    return a;
}
__device__ __forceinline__ void cp_async16(uint32_t saddr, const void* gptr) {
    asm volatile("cp.async.cg.shared.global [%0], [%1], 16;"
                 :: "r"(saddr), "l"(gptr) : "memory");
}
__device__ __forceinline__ void cp_commit() {
    asm volatile("cp.async.commit_group;" ::: "memory");
}
template <int N>
__device__ __forceinline__ void cp_wait() {
    asm volatile("cp.async.wait_group %0;" :: "n"(N) : "memory");
}
__device__ __forceinline__ void ldmatrix_x4(uint32_t& r0, uint32_t& r1,
                                            uint32_t& r2, uint32_t& r3,
                                            uint32_t addr) {
    asm volatile("ldmatrix.sync.aligned.m8n8.x4.shared.b16 {%0,%1,%2,%3}, [%4];"
                 : "=r"(r0), "=r"(r1), "=r"(r2), "=r"(r3) : "r"(addr));
}
__device__ __forceinline__ void mma_16816(float* c, const uint32_t* a,
                                          const uint32_t* b) {
    asm volatile(
        "mma.sync.aligned.m16n8k16.row.col.f32.f16.f16.f32 "
        "{%0,%1,%2,%3}, {%4,%5,%6,%7}, {%8,%9}, {%0,%1,%2,%3};"
        : "+f"(c[0]), "+f"(c[1]), "+f"(c[2]), "+f"(c[3])
        : "r"(a[0]), "r"(a[1]), "r"(a[2]), "r"(a[3]), "r"(b[0]), "r"(b[1]));
}
// smem tile layout: rows of BK fp16 = 64 B = 4 x 16B chunks,
// chunk' = chunk ^ ((row>>1)&3)  -> conflict-free ldmatrix & cp.async stores
__device__ __forceinline__ uint32_t sw_off(int row, int chunk) {
    return (uint32_t)(row * 64 + ((chunk ^ ((row >> 1) & 3)) << 4));
}

// ============================ prep kernels ==================================
__global__ void prep_a_kernel(const float* __restrict__ x) {
    size_t i = (size_t)blockIdx.x * blockDim.x + threadIdx.x;
    const size_t n4 = (size_t)TOKENS * DIN / 4;
    if (i >= n4) return;
    float4 v = __ldg((const float4*)x + i);
    uint32_t h0 = __half_as_ushort(__float2half_rn(v.x))
                | ((uint32_t)__half_as_ushort(__float2half_rn(v.y)) << 16);
    uint32_t h1 = __half_as_ushort(__float2half_rn(v.z))
                | ((uint32_t)__half_as_ushort(__float2half_rn(v.w)) << 16);
    uint2 p; p.x = h0; p.y = h1;
    ((uint2*)g_A)[i] = p;
}
__global__ void prep_b_kernel(const float* __restrict__ w) {
    size_t i = (size_t)blockIdx.x * blockDim.x + threadIdx.x;
    const size_t n4 = (size_t)DOUT * DIN / 4;
    if (i >= n4) return;
    float4 v = __ldg((const float4*)w + i);
    // sign with 0 -> +1 ; fp16 +1.0 = 0x3C00, -1.0 = 0xBC00
    uint32_t s0 = (v.x >= 0.0f) ? 0x3C00u : 0xBC00u;
    uint32_t s1 = (v.y >= 0.0f) ? 0x3C00u : 0xBC00u;
    uint32_t s2 = (v.z >= 0.0f) ? 0x3C00u : 0xBC00u;
    uint32_t s3 = (v.w >= 0.0f) ? 0x3C00u : 0xBC00u;
    uint2 p; p.x = s0 | (s1 << 16); p.y = s2 | (s3 << 16);
    ((uint2*)g_Bs)[i] = p;
}

// ============================ GEMM kernel ===================================
__global__ void __launch_bounds__(THREADS, 1)
qat_gemm_kernel(const float* __restrict__ scale, const float* __restrict__ bias,
                float* __restrict__ out) {
    extern __shared__ char smem[];
    const uint32_t sbase = smem_u32(smem);
    const int tid  = threadIdx.x;
    const int wid  = tid >> 5;
    const int lane = tid & 31;

    // grouped tile swizzle (GROUP_M = 8): 64 m-tiles x 64 n-tiles
    const int pid   = blockIdx.x;
    const int group = pid >> 9;               // / (8*64)
    const int inb   = pid & 511;
    const int pid_m = (group << 3) + (inb & 7);
    const int pid_n = inb >> 3;
    const int m0 = pid_m * BM;
    const int n0 = pid_n * BN;

    // warp tile: 64 (m) x 64 (n); warps: 2 (m) x 4 (n)
    const int warp_m = wid & 1;
    const int warp_n = wid >> 1;
    const int wm0 = warp_m * 64;
    const int wn0 = warp_n * 64;

    // ---- global load indices (16B per cp.async) ----
    // A: 128 rows x 4 chunks = 512 -> 2 per thread (rows r, r+64)
    // B: 256 rows x 4 chunks = 1024 -> 4 per thread (rows r, +64, +128, +192)
    const int g_row = tid >> 2;               // 0..63
    const int g_chk = tid & 3;

    const __half* gA0 = g_A  + (size_t)(m0 + g_row) * DIN + g_chk * 8;
    const __half* gA1 = gA0 + (size_t)64 * DIN;
    const __half* gB0 = g_Bs + (size_t)(n0 + g_row) * DIN + g_chk * 8;
    const __half* gB1 = gB0 + (size_t)64 * DIN;
    const __half* gB2 = gB0 + (size_t)128 * DIN;
    const __half* gB3 = gB0 + (size_t)192 * DIN;

    const uint32_t sA0 = sw_off(g_row,       g_chk);
    const uint32_t sA1 = sw_off(g_row + 64,  g_chk);
    const uint32_t sB0 = sw_off(g_row,       g_chk);
    const uint32_t sB1 = sw_off(g_row + 64,  g_chk);
    const uint32_t sB2 = sw_off(g_row + 128, g_chk);
    const uint32_t sB3 = sw_off(g_row + 192, g_chk);

    auto issue_stage = [&](int c) {
        const int s = c % STAGES;
        const uint32_t stA = sbase + s * STAGE_B;
        const uint32_t stB = stA + A_STAGE_B;
        const size_t kofs = (size_t)c * BK;
        cp_async16(stA + sA0, gA0 + kofs);
        cp_async16(stA + sA1, gA1 + kofs);
        cp_async16(stB + sB0, gB0 + kofs);
        cp_async16(stB + sB1, gB1 + kofs);
        cp_async16(stB + sB2, gB2 + kofs);
        cp_async16(stB + sB3, gB3 + kofs);
    };

    // ---- prologue: fill STAGES-1 stages ----
#pragma unroll
    for (int c = 0; c < STAGES - 1; ++c) { issue_stage(c); cp_commit(); }

    // ---- accumulators: 4 m-frags x 8 n-frags x 4 ----
    float acc[4][8][4];
#pragma unroll
    for (int i = 0; i < 4; ++i)
#pragma unroll
        for (int j = 0; j < 8; ++j)
#pragma unroll
            for (int q = 0; q < 4; ++q) acc[i][j][q] = 0.0f;

    const int lquad = lane >> 3;              // 0..3 : which 8x8 matrix
    const int lrow  = lane & 7;

#pragma unroll 1
    for (int c = 0; c < NCHUNK; ++c) {
        cp_wait<STAGES - 2>();
        __syncthreads();

        // issue next stage into the slot freed by chunk c-1
        if (c + STAGES - 1 < NCHUNK) issue_stage(c + STAGES - 1);
        cp_commit();

        const int s = c % STAGES;
        const uint32_t stA = sbase + s * STAGE_B;
        const uint32_t stB = stA + A_STAGE_B;

#pragma unroll
        for (int kh = 0; kh < 2; ++kh) {      // two k16 halves of BK=32
            const int kchunk = kh * 2;        // 16B-chunk index of k16 base

            // A frags: 4 m16 tiles
            uint32_t afr[4][4];
#pragma unroll
            for (int mi = 0; mi < 4; ++mi) {
                int row = wm0 + mi * 16 + lrow + ((lquad & 1) << 3);
                int chk = kchunk + (lquad >> 1);
                ldmatrix_x4(afr[mi][0], afr[mi][1], afr[mi][2], afr[mi][3],
                            stA + sw_off(row, chk));
            }
            // B frags: 8 n8 tiles, 2 per ldmatrix.x4
            uint32_t bfr[8][2];
#pragma unroll
            for (int jp = 0; jp < 4; ++jp) {
                int row = wn0 + jp * 16 + lrow + ((lquad >> 1) << 3);
                int chk = kchunk + (lquad & 1);
                uint32_t r0, r1, r2, r3;
                ldmatrix_x4(r0, r1, r2, r3, stB + sw_off(row, chk));
                bfr[jp * 2 + 0][0] = r0; bfr[jp * 2 + 0][1] = r1;
                bfr[jp * 2 + 1][0] = r2; bfr[jp * 2 + 1][1] = r3;
            }
#pragma unroll
            for (int mi = 0; mi < 4; ++mi)
#pragma unroll
                for (int j = 0; j < 8; ++j)
                    mma_16816(acc[mi][j], afr[mi], bfr[j]);
        }
        __syncthreads();
    }

    // ---- epilogue: fused scale/bias, float2 stores ----
    const int tq = lane >> 2;                 // 0..7 (row within frag)
    const int tr = lane & 3;                  // col pair selector
#pragma unroll
    for (int j = 0; j < 8; ++j) {
        const int n = n0 + wn0 + j * 8 + 2 * tr;
        const float2 sc = *(const float2*)(scale + n);
        const float2 bb = *(const float2*)(bias + n);
#pragma unroll
        for (int mi = 0; mi < 4; ++mi) {
            const int mrow = m0 + wm0 + mi * 16 + tq;
            float2 v0, v1;
            v0.x = fmaf(sc.x, acc[mi][j][0], bb.x);
            v0.y = fmaf(sc.y, acc[mi][j][1], bb.y);
            v1.x = fmaf(sc.x, acc[mi][j][2], bb.x);
            v1.y = fmaf(sc.y, acc[mi][j][3], bb.y);
            *(float2*)(out + (size_t)mrow * DOUT + n) = v0;
            *(float2*)(out + (size_t)(mrow + 8) * DOUT + n) = v1;
        }
    }
}

// ============================ launch ========================================
extern "C" void kernel_launch(void* const* d_in, const int* in_sizes, int n_in,
                              void* d_out, int out_size) {
    (void)in_sizes; (void)n_in; (void)out_size;
    const float* x     = (const float*)d_in[0];
    const float* w     = (const float*)d_in[1];
    const float* scale = (const float*)d_in[2];
    const float* b     = (const float*)d_in[3];
    float* out = (float*)d_out;

    {
        size_t n4 = (size_t)TOKENS * DIN / 4;
        prep_a_kernel<<<(unsigned)((n4 + 255) / 256), 256>>>(x);
    }
    {
        size_t n4 = (size_t)DOUT * DIN / 4;
        prep_b_kernel<<<(unsigned)((n4 + 255) / 256), 256>>>(w);
    }

    static bool attr_set = false;
    if (!attr_set) {
        cudaFuncSetAttribute(qat_gemm_kernel,
                             cudaFuncAttributeMaxDynamicSharedMemorySize,
                             SMEM_TOTAL);
        attr_set = true;
    }
    const int grid = (TOKENS / BM) * (DOUT / BN);   // 64 * 64 = 4096
    qat_gemm_kernel<<<grid, THREADS, SMEM_TOTAL>>>(scale, b, out);
}

// round 4
// speedup vs baseline: 1.3396x; 1.3396x over previous
#include <cuda_runtime.h>
#include <cuda_fp16.h>
#include <cstdint>

// ============================================================================
// QATLinear: y[t,o] = scale[o] * sum_i x[t,i]*sign(w[o,i]) + b[o]
//
// sign(W)=+-1 exact; x as fp16 (rel err ~2e-4 measured), fp32 mma.sync accum.
// R4: B shipped as PACKED SIGN BITS (1 bit/elem). B smem traffic per chunk
// drops 4KB->256B per warp; fragments expanded in registers (SHF+LOP3).
// Removes the smem-bandwidth co-bind that held R2 at ~63% of the HMMA floor.
// B DRAM footprint 128MB -> 8MB (L2-resident). Single sync per chunk, 6 stages.
// ============================================================================

#define TOKENS 8192
#define DIN    4096
#define DOUT   16384

static constexpr int BM = 128;
static constexpr int BN = 256;
static constexpr int BK = 32;
static constexpr int STAGES = 6;
static constexpr int THREADS = 512;              // 16 warps: 4 (m) x 4 (n)
static constexpr int NCHUNK = DIN / BK;          // 128
static constexpr int KWORDS = DIN / 32;          // 128 words per output row

static constexpr int A_STAGE_B  = BM * BK * 2;   // 8192 B
static constexpr int BW_STAGE_B = BN * 4;        // 1024 B (sign words)
static constexpr int STAGE_B    = A_STAGE_B + BW_STAGE_B;  // 9216
static constexpr int SMEM_TOTAL = STAGES * STAGE_B;        // 55296

// ---- scratch (device globals: allocation-free rule) ----
__device__ __half    g_A [(size_t)TOKENS * DIN];           // 64 MB (x fp16)
__device__ uint32_t  g_Bb[(size_t)KWORDS * DOUT];          // 8 MB (sign bits)
// layout: g_Bb[kc * DOUT + n], bit j = (w[n][kc*32+j] < 0)

// ============================ PTX helpers ===================================
__device__ __forceinline__ uint32_t smem_u32(const void* p) {
    uint32_t a;
    asm("{ .reg .u64 t; cvta.to.shared.u64 t, %1; cvt.u32.u64 %0, t; }"
        : "=r"(a) : "l"(p));
    return a;
}
__device__ __forceinline__ void cp_async16(uint32_t saddr, const void* gptr) {
    asm volatile("cp.async.cg.shared.global [%0], [%1], 16;"
                 :: "r"(saddr), "l"(gptr) : "memory");
}
__device__ __forceinline__ void cp_commit() {
    asm volatile("cp.async.commit_group;" ::: "memory");
}
template <int N>
__device__ __forceinline__ void cp_wait() {
    asm volatile("cp.async.wait_group %0;" :: "n"(N) : "memory");
}
__device__ __forceinline__ void ldmatrix_x4(uint32_t& r0, uint32_t& r1,
                                            uint32_t& r2, uint32_t& r3,
                                            uint32_t addr) {
    asm volatile("ldmatrix.sync.aligned.m8n8.x4.shared.b16 {%0,%1,%2,%3}, [%4];"
                 : "=r"(r0), "=r"(r1), "=r"(r2), "=r"(r3) : "r"(addr));
}
__device__ __forceinline__ uint32_t lds32(uint32_t addr) {
    uint32_t v;
    asm volatile("ld.shared.b32 %0, [%1];" : "=r"(v) : "r"(addr));
    return v;
}
__device__ __forceinline__ void mma_16816(float* c, const uint32_t* a,
                                          const uint32_t* b) {
    asm volatile(
        "mma.sync.aligned.m16n8k16.row.col.f32.f16.f16.f32 "
        "{%0,%1,%2,%3}, {%4,%5,%6,%7}, {%8,%9}, {%0,%1,%2,%3};"
        : "+f"(c[0]), "+f"(c[1]), "+f"(c[2]), "+f"(c[3])
        : "r"(a[0]), "r"(a[1]), "r"(a[2]), "r"(a[3]), "r"(b[0]), "r"(b[1]));
}
// A smem tile: rows of BK fp16 = 64 B = 4 x 16B chunks,
// chunk' = chunk ^ ((row>>1)&3)  -> conflict-free ldmatrix & cp.async stores
__device__ __forceinline__ uint32_t sw_off(int row, int chunk) {
    return (uint32_t)(row * 64 + ((chunk ^ ((row >> 1) & 3)) << 4));
}

// ============================ prep kernels ==================================
__global__ void prep_a_kernel(const float* __restrict__ x) {
    size_t i = (size_t)blockIdx.x * blockDim.x + threadIdx.x;
    const size_t n4 = (size_t)TOKENS * DIN / 4;
    if (i >= n4) return;
    float4 v = __ldg((const float4*)x + i);
    uint32_t h0 = __half_as_ushort(__float2half_rn(v.x))
                | ((uint32_t)__half_as_ushort(__float2half_rn(v.y)) << 16);
    uint32_t h1 = __half_as_ushort(__float2half_rn(v.z))
                | ((uint32_t)__half_as_ushort(__float2half_rn(v.w)) << 16);
    uint2 p; p.x = h0; p.y = h1;
    ((uint2*)g_A)[i] = p;
}
// sign-bit packing via warp ballot; bit=1 <=> w<0 (0,-0 -> +1 like reference)
__global__ void prep_b_kernel(const float* __restrict__ w) {
    size_t g = (size_t)blockIdx.x * blockDim.x + threadIdx.x;  // over DOUT*DIN
    float v = __ldg(w + g);
    uint32_t word = __ballot_sync(0xFFFFFFFFu, v < 0.0f);
    if ((threadIdx.x & 31) == 0) {
        size_t n  = g / DIN;
        size_t kc = (g % DIN) >> 5;
        g_Bb[kc * DOUT + n] = word;
    }
}

// ============================ GEMM kernel ===================================
__global__ void __launch_bounds__(THREADS, 1)
qat_gemm_kernel(const float* __restrict__ scale, const float* __restrict__ bias,
                float* __restrict__ out) {
    extern __shared__ char smem[];
    const uint32_t sbase = smem_u32(smem);
    const int tid  = threadIdx.x;
    const int wid  = tid >> 5;
    const int lane = tid & 31;

    // grouped tile swizzle (GROUP_M = 8): 64 m-tiles x 64 n-tiles
    const int pid   = blockIdx.x;
    const int group = pid >> 9;               // / (8*64)
    const int inb   = pid & 511;
    const int pid_m = (group << 3) + (inb & 7);
    const int pid_n = inb >> 3;
    const int m0 = pid_m * BM;
    const int n0 = pid_n * BN;

    // warp tile: 32 (m) x 64 (n); warps: 4 (m) x 4 (n)
    const int warp_m = wid & 3;
    const int warp_n = wid >> 2;
    const int wm0 = warp_m * 32;
    const int wn0 = warp_n * 64;

    // ---- global load indices ----
    // A: 128 rows x 4 chunks = 512 x 16B -> 1 per thread
    const int a_row = tid >> 2, a_chk = tid & 3;
    const __half* gA = g_A + (size_t)(m0 + a_row) * DIN + a_chk * 8;
    const uint32_t sA_off = sw_off(a_row, a_chk);
    // B words: 256 x 4B = 1KB -> threads 0..63, 16B each
    const uint32_t* gBw = g_Bb + n0;

    auto issue_stage = [&](int c) {
        const int s = c % STAGES;
        const uint32_t stA = sbase + s * STAGE_B;
        cp_async16(stA + sA_off, gA + (size_t)c * BK);
        if (tid < 64) {
            cp_async16(stA + A_STAGE_B + tid * 16,
                       gBw + (size_t)c * DOUT + tid * 4);
        }
    };

    // ---- prologue: fill STAGES-1 stages ----
#pragma unroll
    for (int c = 0; c < STAGES - 1; ++c) { issue_stage(c); cp_commit(); }

    // ---- accumulators: 2 m-frags x 8 n-frags x 4 ----
    float acc[2][8][4];
#pragma unroll
    for (int i = 0; i < 2; ++i)
#pragma unroll
        for (int j = 0; j < 8; ++j)
#pragma unroll
            for (int q = 0; q < 4; ++q) acc[i][j][q] = 0.0f;

    const int lquad = lane >> 3;              // ldmatrix addressing
    const int lrow  = lane & 7;
    const int q2    = (lane & 3) << 1;        // 2*(lane%4) for b-frag bits
    const uint32_t wb_base = (uint32_t)((wn0 + (lane >> 2)) * 4);

#pragma unroll 1
    for (int c = 0; c < NCHUNK; ++c) {
        cp_wait<STAGES - 2>();
        __syncthreads();        // single sync: readers of stage c-1 all arrived

        if (c + STAGES - 1 < NCHUNK) issue_stage(c + STAGES - 1);
        cp_commit();

        const int s = c % STAGES;
        const uint32_t stA  = sbase + s * STAGE_B;
        const uint32_t stBw = stA + A_STAGE_B;

        // B sign words for this warp's 64 n-cols: 8 words/lane (quad-broadcast)
        uint32_t wbits[8];
#pragma unroll
        for (int jp = 0; jp < 8; ++jp)
            wbits[jp] = lds32(stBw + wb_base + jp * 32);

#pragma unroll
        for (int kh = 0; kh < 2; ++kh) {      // two k16 halves of BK=32
            const int kchunk = kh * 2;

            // A frags: 2 m16 tiles via ldmatrix.x4
            uint32_t afr[2][4];
#pragma unroll
            for (int mi = 0; mi < 2; ++mi) {
                int row = wm0 + mi * 16 + lrow + ((lquad & 1) << 3);
                int chk = kchunk + (lquad >> 1);
                ldmatrix_x4(afr[mi][0], afr[mi][1], afr[mi][2], afr[mi][3],
                            stA + sw_off(row, chk));
            }

            const int sh = kh * 16 + q2;
#pragma unroll
            for (int jp = 0; jp < 8; ++jp) {
                // expand +-1 b-frag from sign bits:
                // b0: k = kh*16 + 2q {,+1}; b1: +8. sign bit -> fp16 sign.
                uint32_t t  = wbits[jp] >> sh;
                uint32_t b[2];
                b[0] = 0x3C003C00u | ((t & 1u) << 15) | ((t & 2u) << 30);
                uint32_t t8 = t >> 8;
                b[1] = 0x3C003C00u | ((t8 & 1u) << 15) | ((t8 & 2u) << 30);
                mma_16816(acc[0][jp], afr[0], b);
                mma_16816(acc[1][jp], afr[1], b);
            }
        }
    }

    // ---- epilogue: fused scale/bias, float2 stores ----
    const int tq = lane >> 2;                 // row within frag
    const int tr = lane & 3;                  // col pair selector
#pragma unroll
    for (int j = 0; j < 8; ++j) {
        const int n = n0 + wn0 + j * 8 + 2 * tr;
        const float2 sc = *(const float2*)(scale + n);
        const float2 bb = *(const float2*)(bias + n);
#pragma unroll
        for (int mi = 0; mi < 2; ++mi) {
            const int mrow = m0 + wm0 + mi * 16 + tq;
            float2 v0, v1;
            v0.x = fmaf(sc.x, acc[mi][j][0], bb.x);
            v0.y = fmaf(sc.y, acc[mi][j][1], bb.y);
            v1.x = fmaf(sc.x, acc[mi][j][2], bb.x);
            v1.y = fmaf(sc.y, acc[mi][j][3], bb.y);
            *(float2*)(out + (size_t)mrow * DOUT + n) = v0;
            *(float2*)(out + (size_t)(mrow + 8) * DOUT + n) = v1;
        }
    }
}

// ============================ launch ========================================
extern "C" void kernel_launch(void* const* d_in, const int* in_sizes, int n_in,
                              void* d_out, int out_size) {
    (void)in_sizes; (void)n_in; (void)out_size;
    const float* x     = (const float*)d_in[0];
    const float* w     = (const float*)d_in[1];
    const float* scale = (const float*)d_in[2];
    const float* b     = (const float*)d_in[3];
    float* out = (float*)d_out;

    {
        size_t n4 = (size_t)TOKENS * DIN / 4;
        prep_a_kernel<<<(unsigned)((n4 + 255) / 256), 256>>>(x);
    }
    {
        size_t nt = (size_t)DOUT * DIN;          // one thread per element
        prep_b_kernel<<<(unsigned)((nt + 255) / 256), 256>>>(w);
    }

    cudaFuncSetAttribute(qat_gemm_kernel,
                         cudaFuncAttributeMaxDynamicSharedMemorySize,
                         SMEM_TOTAL);
    const int grid = (TOKENS / BM) * (DOUT / BN);   // 64 * 64 = 4096
    qat_gemm_kernel<<<grid, THREADS, SMEM_TOTAL>>>(scale, b, out);
}

// round 5
// speedup vs baseline: 1.8014x; 1.3447x over previous
#include <cuda_runtime.h>
#include <cuda_fp16.h>
#include <cstdint>

// ============================================================================
// QATLinear: y[t,o] = scale[o] * sum_i x[t,i]*sign(w[o,i]) + b[o]
//
// sign(W)=+-1 exact in fp16; x as fp16 (rel err 2.1e-4 measured), fp32
// mma.sync accumulation. Register-path m16n8k16 (compute_103: no tcgen05).
//
// R5: revert R4 bit-packing (ALU expansion stalled the MMA stream).
// Back to R2 skeleton, but BK 32->64 and ONE __syncthreads per chunk:
// halves the per-chunk serial overhead count (barriers + cold ldmatrix
// latency chain after each barrier) that held R2 at ~67% of the HMMA floor.
// STAGES=3 x 48KB = 144KB smem.
// ============================================================================

#define TOKENS 8192
#define DIN    4096
#define DOUT   16384

static constexpr int BM = 128;
static constexpr int BN = 256;
static constexpr int BK = 64;
static constexpr int STAGES = 3;
static constexpr int THREADS = 512;              // 16 warps: 4 (m) x 4 (n)
static constexpr int NCHUNK = DIN / BK;          // 64

static constexpr int A_STAGE_B = BM * BK * 2;    // 16384 B
static constexpr int B_STAGE_B = BN * BK * 2;    // 32768 B
static constexpr int STAGE_B   = A_STAGE_B + B_STAGE_B;   // 49152
static constexpr int SMEM_TOTAL = STAGES * STAGE_B;       // 147456

// ---- scratch (device globals: allocation-free rule) ----
__device__ __half g_A [(size_t)TOKENS * DIN];    // 64 MB  (x as fp16)
__device__ __half g_Bs[(size_t)DOUT  * DIN];     // 128 MB (sign(w) as fp16)

// ============================ PTX helpers ===================================
__device__ __forceinline__ uint32_t smem_u32(const void* p) {
    uint32_t a;
    asm("{ .reg .u64 t; cvta.to.shared.u64 t, %1; cvt.u32.u64 %0, t; }"
        : "=r"(a) : "l"(p));
    return a;
}
__device__ __forceinline__ void cp_async16(uint32_t saddr, const void* gptr) {
    asm volatile("cp.async.cg.shared.global [%0], [%1], 16;"
                 :: "r"(saddr), "l"(gptr) : "memory");
}
__device__ __forceinline__ void cp_commit() {
    asm volatile("cp.async.commit_group;" ::: "memory");
}
template <int N>
__device__ __forceinline__ void cp_wait() {
    asm volatile("cp.async.wait_group %0;" :: "n"(N) : "memory");
}
__device__ __forceinline__ void ldmatrix_x4(uint32_t& r0, uint32_t& r1,
                                            uint32_t& r2, uint32_t& r3,
                                            uint32_t addr) {
    asm volatile("ldmatrix.sync.aligned.m8n8.x4.shared.b16 {%0,%1,%2,%3}, [%4];"
                 : "=r"(r0), "=r"(r1), "=r"(r2), "=r"(r3) : "r"(addr));
}
__device__ __forceinline__ void mma_16816(float* c, const uint32_t* a,
                                          const uint32_t* b) {
    asm volatile(
        "mma.sync.aligned.m16n8k16.row.col.f32.f16.f16.f32 "
        "{%0,%1,%2,%3}, {%4,%5,%6,%7}, {%8,%9}, {%0,%1,%2,%3};"
        : "+f"(c[0]), "+f"(c[1]), "+f"(c[2]), "+f"(c[3])
        : "r"(a[0]), "r"(a[1]), "r"(a[2]), "r"(a[3]), "r"(b[0]), "r"(b[1]));
}
// smem tile rows: BK fp16 = 128 B = 8 x 16B chunks; chunk' = chunk ^ (row&7)
// -> 8-row ldmatrix reads cover all 32 banks exactly once (conflict-free),
//    cp.async 16B stores land in distinct banks per row.
__device__ __forceinline__ uint32_t sw_off(int row, int chunk) {
    return (uint32_t)((row << 7) + ((chunk ^ (row & 7)) << 4));
}

// ============================ prep kernels ==================================
__global__ void prep_a_kernel(const float* __restrict__ x) {
    size_t i = (size_t)blockIdx.x * blockDim.x + threadIdx.x;
    const size_t n4 = (size_t)TOKENS * DIN / 4;
    if (i >= n4) return;
    float4 v = __ldg((const float4*)x + i);
    uint32_t h0 = __half_as_ushort(__float2half_rn(v.x))
                | ((uint32_t)__half_as_ushort(__float2half_rn(v.y)) << 16);
    uint32_t h1 = __half_as_ushort(__float2half_rn(v.z))
                | ((uint32_t)__half_as_ushort(__float2half_rn(v.w)) << 16);
    uint2 p; p.x = h0; p.y = h1;
    ((uint2*)g_A)[i] = p;
}
__global__ void prep_b_kernel(const float* __restrict__ w) {
    size_t i = (size_t)blockIdx.x * blockDim.x + threadIdx.x;
    const size_t n4 = (size_t)DOUT * DIN / 4;
    if (i >= n4) return;
    float4 v = __ldg((const float4*)w + i);
    // sign with 0 -> +1 ; fp16 +1.0 = 0x3C00, -1.0 = 0xBC00
    uint32_t s0 = (v.x >= 0.0f) ? 0x3C00u : 0xBC00u;
    uint32_t s1 = (v.y >= 0.0f) ? 0x3C00u : 0xBC00u;
    uint32_t s2 = (v.z >= 0.0f) ? 0x3C00u : 0xBC00u;
    uint32_t s3 = (v.w >= 0.0f) ? 0x3C00u : 0xBC00u;
    uint2 p; p.x = s0 | (s1 << 16); p.y = s2 | (s3 << 16);
    ((uint2*)g_Bs)[i] = p;
}

// ============================ GEMM kernel ===================================
__global__ void __launch_bounds__(THREADS, 1)
qat_gemm_kernel(const float* __restrict__ scale, const float* __restrict__ bias,
                float* __restrict__ out) {
    extern __shared__ char smem[];
    const uint32_t sbase = smem_u32(smem);
    const int tid  = threadIdx.x;
    const int wid  = tid >> 5;
    const int lane = tid & 31;

    // grouped tile swizzle (GROUP_M = 8): 64 m-tiles x 64 n-tiles
    const int pid   = blockIdx.x;
    const int group = pid >> 9;               // / (8*64)
    const int inb   = pid & 511;
    const int pid_m = (group << 3) + (inb & 7);
    const int pid_n = inb >> 3;
    const int m0 = pid_m * BM;
    const int n0 = pid_n * BN;

    // warp tile: 32 (m) x 64 (n); warps: 4 (m) x 4 (n)
    const int warp_m = wid & 3;
    const int warp_n = wid >> 2;
    const int wm0 = warp_m * 32;
    const int wn0 = warp_n * 64;

    // ---- global load indices (16B per cp.async; rows are 8x16B chunks) ----
    const int g_row = tid >> 3;               // 0..63
    const int g_chk = tid & 7;

    const __half* gA0 = g_A  + (size_t)(m0 + g_row) * DIN + g_chk * 8;
    const __half* gA1 = gA0 + (size_t)64 * DIN;
    const __half* gB0 = g_Bs + (size_t)(n0 + g_row) * DIN + g_chk * 8;
    const __half* gB1 = gB0 + (size_t)64 * DIN;
    const __half* gB2 = gB0 + (size_t)128 * DIN;
    const __half* gB3 = gB0 + (size_t)192 * DIN;

    const uint32_t sA0 = sw_off(g_row,       g_chk);
    const uint32_t sA1 = sw_off(g_row + 64,  g_chk);
    const uint32_t sB0 = sw_off(g_row,       g_chk);
    const uint32_t sB1 = sw_off(g_row + 64,  g_chk);
    const uint32_t sB2 = sw_off(g_row + 128, g_chk);
    const uint32_t sB3 = sw_off(g_row + 192, g_chk);

    auto issue_stage = [&](int c) {
        const int s = c % STAGES;
        const uint32_t stA = sbase + s * STAGE_B;
        const uint32_t stB = stA + A_STAGE_B;
        const size_t kofs = (size_t)c * BK;
        cp_async16(stA + sA0, gA0 + kofs);
        cp_async16(stA + sA1, gA1 + kofs);
        cp_async16(stB + sB0, gB0 + kofs);
        cp_async16(stB + sB1, gB1 + kofs);
        cp_async16(stB + sB2, gB2 + kofs);
        cp_async16(stB + sB3, gB3 + kofs);
    };

    // ---- prologue: fill STAGES-1 stages ----
#pragma unroll
    for (int c = 0; c < STAGES - 1; ++c) { issue_stage(c); cp_commit(); }

    // ---- accumulators: 2 m-frags x 8 n-frags x 4 ----
    float acc[2][8][4];
#pragma unroll
    for (int i = 0; i < 2; ++i)
#pragma unroll
        for (int j = 0; j < 8; ++j)
#pragma unroll
            for (int q = 0; q < 4; ++q) acc[i][j][q] = 0.0f;

    const int lquad = lane >> 3;              // 0..3 : which 8x8 matrix
    const int lrow  = lane & 7;

#pragma unroll 1
    for (int c = 0; c < NCHUNK; ++c) {
        cp_wait<STAGES - 2>();
        __syncthreads();   // single barrier: all warps done reading stage c-1

        if (c + STAGES - 1 < NCHUNK) issue_stage(c + STAGES - 1);
        cp_commit();

        const int s = c % STAGES;
        const uint32_t stA = sbase + s * STAGE_B;
        const uint32_t stB = stA + A_STAGE_B;

#pragma unroll
        for (int kh = 0; kh < 4; ++kh) {      // four k16 halves of BK=64
            const int kchunk = kh * 2;        // 16B-chunk index of k16 base

            // A frags: 2 m16 tiles
            uint32_t afr[2][4];
#pragma unroll
            for (int mi = 0; mi < 2; ++mi) {
                int row = wm0 + mi * 16 + lrow + ((lquad & 1) << 3);
                int chk = kchunk + (lquad >> 1);
                ldmatrix_x4(afr[mi][0], afr[mi][1], afr[mi][2], afr[mi][3],
                            stA + sw_off(row, chk));
            }
            // B frags: 8 n8 tiles, 2 per ldmatrix.x4
            uint32_t bfr[8][2];
#pragma unroll
            for (int jp = 0; jp < 4; ++jp) {
                int row = wn0 + jp * 16 + lrow + ((lquad >> 1) << 3);
                int chk = kchunk + (lquad & 1);
                uint32_t r0, r1, r2, r3;
                ldmatrix_x4(r0, r1, r2, r3, stB + sw_off(row, chk));
                bfr[jp * 2 + 0][0] = r0; bfr[jp * 2 + 0][1] = r1;
                bfr[jp * 2 + 1][0] = r2; bfr[jp * 2 + 1][1] = r3;
            }
#pragma unroll
            for (int mi = 0; mi < 2; ++mi)
#pragma unroll
                for (int j = 0; j < 8; ++j)
                    mma_16816(acc[mi][j], afr[mi], bfr[j]);
        }
    }

    // ---- epilogue: fused scale/bias, float2 stores ----
    const int tq = lane >> 2;                 // 0..7 (row within frag)
    const int tr = lane & 3;                  // col pair selector
#pragma unroll
    for (int j = 0; j < 8; ++j) {
        const int n = n0 + wn0 + j * 8 + 2 * tr;
        const float2 sc = *(const float2*)(scale + n);
        const float2 bb = *(const float2*)(bias + n);
#pragma unroll
        for (int mi = 0; mi < 2; ++mi) {
            const int mrow = m0 + wm0 + mi * 16 + tq;
            float2 v0, v1;
            v0.x = fmaf(sc.x, acc[mi][j][0], bb.x);
            v0.y = fmaf(sc.y, acc[mi][j][1], bb.y);
            v1.x = fmaf(sc.x, acc[mi][j][2], bb.x);
            v1.y = fmaf(sc.y, acc[mi][j][3], bb.y);
            *(float2*)(out + (size_t)mrow * DOUT + n) = v0;
            *(float2*)(out + (size_t)(mrow + 8) * DOUT + n) = v1;
        }
    }
}

// ============================ launch ========================================
extern "C" void kernel_launch(void* const* d_in, const int* in_sizes, int n_in,
                              void* d_out, int out_size) {
    (void)in_sizes; (void)n_in; (void)out_size;
    const float* x     = (const float*)d_in[0];
    const float* w     = (const float*)d_in[1];
    const float* scale = (const float*)d_in[2];
    const float* b     = (const float*)d_in[3];
    float* out = (float*)d_out;

    {
        size_t n4 = (size_t)TOKENS * DIN / 4;
        prep_a_kernel<<<(unsigned)((n4 + 255) / 256), 256>>>(x);
    }
    {
        size_t n4 = (size_t)DOUT * DIN / 4;
        prep_b_kernel<<<(unsigned)((n4 + 255) / 256), 256>>>(w);
    }

    cudaFuncSetAttribute(qat_gemm_kernel,
                         cudaFuncAttributeMaxDynamicSharedMemorySize,
                         SMEM_TOTAL);
    const int grid = (TOKENS / BM) * (DOUT / BN);   // 64 * 64 = 4096
    qat_gemm_kernel<<<grid, THREADS, SMEM_TOTAL>>>(scale, b, out);
}

// round 6
// speedup vs baseline: 1.9804x; 1.0993x over previous
#include <cuda_runtime.h>
#include <cuda_fp16.h>
#include <cstdint>

// ============================================================================
// QATLinear: y[t,o] = scale[o] * sum_i x[t,i]*sign(w[o,i]) + b[o]
//
// sign(W)=+-1 exact in fp16; x as fp16 (rel err 2.1e-4), fp32 mma.sync accum.
// R6: 2 CTAs/SM co-residency to hide per-chunk barrier + cold-LDS latency.
// BM=128 BN=128, 256 threads (8 warps, warp tile 32x64), STAGES=3 (96KB/CTA),
// __launch_bounds__(256,2) so RF (2x256x128=64K) and smem (192KB) both fit 2.
// ============================================================================

#define TOKENS 8192
#define DIN    4096
#define DOUT   16384

static constexpr int BM = 128;
static constexpr int BN = 128;
static constexpr int BK = 64;
static constexpr int STAGES = 3;
static constexpr int THREADS = 256;              // 8 warps: 4 (m) x 2 (n)
static constexpr int NCHUNK = DIN / BK;          // 64

static constexpr int A_STAGE_B = BM * BK * 2;    // 16384 B
static constexpr int B_STAGE_B = BN * BK * 2;    // 16384 B
static constexpr int STAGE_B   = A_STAGE_B + B_STAGE_B;   // 32768
static constexpr int SMEM_TOTAL = STAGES * STAGE_B;       // 98304 per CTA

// ---- scratch (device globals: allocation-free rule) ----
__device__ __half g_A [(size_t)TOKENS * DIN];    // 64 MB  (x as fp16)
__device__ __half g_Bs[(size_t)DOUT  * DIN];     // 128 MB (sign(w) as fp16)

// ============================ PTX helpers ===================================
__device__ __forceinline__ uint32_t smem_u32(const void* p) {
    uint32_t a;
    asm("{ .reg .u64 t; cvta.to.shared.u64 t, %1; cvt.u32.u64 %0, t; }"
        : "=r"(a) : "l"(p));
    return a;
}
__device__ __forceinline__ void cp_async16(uint32_t saddr, const void* gptr) {
    asm volatile("cp.async.cg.shared.global [%0], [%1], 16;"
                 :: "r"(saddr), "l"(gptr) : "memory");
}
__device__ __forceinline__ void cp_commit() {
    asm volatile("cp.async.commit_group;" ::: "memory");
}
template <int N>
__device__ __forceinline__ void cp_wait() {
    asm volatile("cp.async.wait_group %0;" :: "n"(N) : "memory");
}
__device__ __forceinline__ void ldmatrix_x4(uint32_t& r0, uint32_t& r1,
                                            uint32_t& r2, uint32_t& r3,
                                            uint32_t addr) {
    asm volatile("ldmatrix.sync.aligned.m8n8.x4.shared.b16 {%0,%1,%2,%3}, [%4];"
                 : "=r"(r0), "=r"(r1), "=r"(r2), "=r"(r3) : "r"(addr));
}
__device__ __forceinline__ void mma_16816(float* c, const uint32_t* a,
                                          const uint32_t* b) {
    asm volatile(
        "mma.sync.aligned.m16n8k16.row.col.f32.f16.f16.f32 "
        "{%0,%1,%2,%3}, {%4,%5,%6,%7}, {%8,%9}, {%0,%1,%2,%3};"
        : "+f"(c[0]), "+f"(c[1]), "+f"(c[2]), "+f"(c[3])
        : "r"(a[0]), "r"(a[1]), "r"(a[2]), "r"(a[3]), "r"(b[0]), "r"(b[1]));
}
// smem tile rows: BK fp16 = 128 B = 8 x 16B chunks; chunk' = chunk ^ (row&7)
__device__ __forceinline__ uint32_t sw_off(int row, int chunk) {
    return (uint32_t)((row << 7) + ((chunk ^ (row & 7)) << 4));
}

// ============================ prep kernels ==================================
__global__ void prep_a_kernel(const float* __restrict__ x) {
    size_t i = (size_t)blockIdx.x * blockDim.x + threadIdx.x;
    const size_t n4 = (size_t)TOKENS * DIN / 4;
    if (i >= n4) return;
    float4 v = __ldg((const float4*)x + i);
    uint32_t h0 = __half_as_ushort(__float2half_rn(v.x))
                | ((uint32_t)__half_as_ushort(__float2half_rn(v.y)) << 16);
    uint32_t h1 = __half_as_ushort(__float2half_rn(v.z))
                | ((uint32_t)__half_as_ushort(__float2half_rn(v.w)) << 16);
    uint2 p; p.x = h0; p.y = h1;
    ((uint2*)g_A)[i] = p;
}
__global__ void prep_b_kernel(const float* __restrict__ w) {
    size_t i = (size_t)blockIdx.x * blockDim.x + threadIdx.x;
    const size_t n4 = (size_t)DOUT * DIN / 4;
    if (i >= n4) return;
    float4 v = __ldg((const float4*)w + i);
    uint32_t s0 = (v.x >= 0.0f) ? 0x3C00u : 0xBC00u;
    uint32_t s1 = (v.y >= 0.0f) ? 0x3C00u : 0xBC00u;
    uint32_t s2 = (v.z >= 0.0f) ? 0x3C00u : 0xBC00u;
    uint32_t s3 = (v.w >= 0.0f) ? 0x3C00u : 0xBC00u;
    uint2 p; p.x = s0 | (s1 << 16); p.y = s2 | (s3 << 16);
    ((uint2*)g_Bs)[i] = p;
}

// ============================ GEMM kernel ===================================
__global__ void __launch_bounds__(THREADS, 2)
qat_gemm_kernel(const float* __restrict__ scale, const float* __restrict__ bias,
                float* __restrict__ out) {
    extern __shared__ char smem[];
    const uint32_t sbase = smem_u32(smem);
    const int tid  = threadIdx.x;
    const int wid  = tid >> 5;
    const int lane = tid & 31;

    // grouped tile swizzle (GROUP_M = 8): 64 m-tiles x 128 n-tiles
    const int pid   = blockIdx.x;                 // 0 .. 8191
    const int group = pid >> 10;                  // / (8*128)
    const int inb   = pid & 1023;
    const int pid_m = (group << 3) + (inb & 7);
    const int pid_n = inb >> 3;
    const int m0 = pid_m * BM;
    const int n0 = pid_n * BN;

    // warp tile: 32 (m) x 64 (n); warps: 4 (m) x 2 (n)
    const int warp_m = wid & 3;
    const int warp_n = wid >> 2;
    const int wm0 = warp_m * 32;
    const int wn0 = warp_n * 64;

    // ---- global load indices (16B per cp.async; rows are 8x16B chunks) ----
    const int g_row = tid >> 3;               // 0..31
    const int g_chk = tid & 7;

    const __half* gA0 = g_A  + (size_t)(m0 + g_row) * DIN + g_chk * 8;
    const __half* gA1 = gA0 + (size_t)32 * DIN;
    const __half* gA2 = gA0 + (size_t)64 * DIN;
    const __half* gA3 = gA0 + (size_t)96 * DIN;
    const __half* gB0 = g_Bs + (size_t)(n0 + g_row) * DIN + g_chk * 8;
    const __half* gB1 = gB0 + (size_t)32 * DIN;
    const __half* gB2 = gB0 + (size_t)64 * DIN;
    const __half* gB3 = gB0 + (size_t)96 * DIN;

    const uint32_t sO0 = sw_off(g_row,      g_chk);
    const uint32_t sO1 = sw_off(g_row + 32, g_chk);
    const uint32_t sO2 = sw_off(g_row + 64, g_chk);
    const uint32_t sO3 = sw_off(g_row + 96, g_chk);

    auto issue_stage = [&](int c) {
        const int s = c % STAGES;
        const uint32_t stA = sbase + s * STAGE_B;
        const uint32_t stB = stA + A_STAGE_B;
        const size_t kofs = (size_t)c * BK;
        cp_async16(stA + sO0, gA0 + kofs);
        cp_async16(stA + sO1, gA1 + kofs);
        cp_async16(stA + sO2, gA2 + kofs);
        cp_async16(stA + sO3, gA3 + kofs);
        cp_async16(stB + sO0, gB0 + kofs);
        cp_async16(stB + sO1, gB1 + kofs);
        cp_async16(stB + sO2, gB2 + kofs);
        cp_async16(stB + sO3, gB3 + kofs);
    };

    // ---- prologue: fill STAGES-1 stages ----
#pragma unroll
    for (int c = 0; c < STAGES - 1; ++c) { issue_stage(c); cp_commit(); }

    // ---- accumulators: 2 m-frags x 8 n-frags x 4 ----
    float acc[2][8][4];
#pragma unroll
    for (int i = 0; i < 2; ++i)
#pragma unroll
        for (int j = 0; j < 8; ++j)
#pragma unroll
            for (int q = 0; q < 4; ++q) acc[i][j][q] = 0.0f;

    const int lquad = lane >> 3;              // 0..3 : which 8x8 matrix
    const int lrow  = lane & 7;

#pragma unroll 1
    for (int c = 0; c < NCHUNK; ++c) {
        cp_wait<STAGES - 2>();
        __syncthreads();   // single barrier: all warps done reading stage c-1

        if (c + STAGES - 1 < NCHUNK) issue_stage(c + STAGES - 1);
        cp_commit();

        const int s = c % STAGES;
        const uint32_t stA = sbase + s * STAGE_B;
        const uint32_t stB = stA + A_STAGE_B;

#pragma unroll
        for (int kh = 0; kh < 4; ++kh) {      // four k16 halves of BK=64
            const int kchunk = kh * 2;        // 16B-chunk index of k16 base

            // A frags: 2 m16 tiles
            uint32_t afr[2][4];
#pragma unroll
            for (int mi = 0; mi < 2; ++mi) {
                int row = wm0 + mi * 16 + lrow + ((lquad & 1) << 3);
                int chk = kchunk + (lquad >> 1);
                ldmatrix_x4(afr[mi][0], afr[mi][1], afr[mi][2], afr[mi][3],
                            stA + sw_off(row, chk));
            }
            // B frags: 8 n8 tiles, 2 per ldmatrix.x4
            uint32_t bfr[8][2];
#pragma unroll
            for (int jp = 0; jp < 4; ++jp) {
                int row = wn0 + jp * 16 + lrow + ((lquad >> 1) << 3);
                int chk = kchunk + (lquad & 1);
                uint32_t r0, r1, r2, r3;
                ldmatrix_x4(r0, r1, r2, r3, stB + sw_off(row, chk));
                bfr[jp * 2 + 0][0] = r0; bfr[jp * 2 + 0][1] = r1;
                bfr[jp * 2 + 1][0] = r2; bfr[jp * 2 + 1][1] = r3;
            }
#pragma unroll
            for (int mi = 0; mi < 2; ++mi)
#pragma unroll
                for (int j = 0; j < 8; ++j)
                    mma_16816(acc[mi][j], afr[mi], bfr[j]);
        }
    }

    // ---- epilogue: fused scale/bias, float2 stores ----
    const int tq = lane >> 2;                 // 0..7 (row within frag)
    const int tr = lane & 3;                  // col pair selector
#pragma unroll
    for (int j = 0; j < 8; ++j) {
        const int n = n0 + wn0 + j * 8 + 2 * tr;
        const float2 sc = *(const float2*)(scale + n);
        const float2 bb = *(const float2*)(bias + n);
#pragma unroll
        for (int mi = 0; mi < 2; ++mi) {
            const int mrow = m0 + wm0 + mi * 16 + tq;
            float2 v0, v1;
            v0.x = fmaf(sc.x, acc[mi][j][0], bb.x);
            v0.y = fmaf(sc.y, acc[mi][j][1], bb.y);
            v1.x = fmaf(sc.x, acc[mi][j][2], bb.x);
            v1.y = fmaf(sc.y, acc[mi][j][3], bb.y);
            *(float2*)(out + (size_t)mrow * DOUT + n) = v0;
            *(float2*)(out + (size_t)(mrow + 8) * DOUT + n) = v1;
        }
    }
}

// ============================ launch ========================================
extern "C" void kernel_launch(void* const* d_in, const int* in_sizes, int n_in,
                              void* d_out, int out_size) {
    (void)in_sizes; (void)n_in; (void)out_size;
    const float* x     = (const float*)d_in[0];
    const float* w     = (const float*)d_in[1];
    const float* scale = (const float*)d_in[2];
    const float* b     = (const float*)d_in[3];
    float* out = (float*)d_out;

    {
        size_t n4 = (size_t)TOKENS * DIN / 4;
        prep_a_kernel<<<(unsigned)((n4 + 255) / 256), 256>>>(x);
    }
    {
        size_t n4 = (size_t)DOUT * DIN / 4;
        prep_b_kernel<<<(unsigned)((n4 + 255) / 256), 256>>>(w);
    }

    cudaFuncSetAttribute(qat_gemm_kernel,
                         cudaFuncAttributeMaxDynamicSharedMemorySize,
                         SMEM_TOTAL);
    const int grid = (TOKENS / BM) * (DOUT / BN);   // 64 * 128 = 8192
    qat_gemm_kernel<<<grid, THREADS, SMEM_TOTAL>>>(scale, b, out);
}

// round 7
// speedup vs baseline: 2.0389x; 1.0296x over previous
#include <cuda_runtime.h>
#include <cuda_fp16.h>
#include <cstdint>

// ============================================================================
// QATLinear: y[t,o] = scale[o] * sum_i x[t,i]*sign(w[o,i]) + b[o]
//
// sign(W)=+-1 exact in fp16; x as fp16, fp32 mma.sync accumulation.
// R7: phase-stagger the two co-resident CTAs' chunk loops (rotate start by
// NCHUNK/2 based on wave parity) so their per-chunk barriers + cold-LDSM
// bursts anti-align: one CTA's tensor stream covers the other's refill
// window. fp32 accumulation order changes (allowed; rel_err ~2e-4 << 1e-3).
// Core config unchanged from R6: BM=BN=128, BK=64, 8 warps (32x64 warp tile),
// STAGES=3 (96KB/CTA), __launch_bounds__(256,2) => 2 CTAs/SM.
// ============================================================================

#define TOKENS 8192
#define DIN    4096
#define DOUT   16384

static constexpr int BM = 128;
static constexpr int BN = 128;
static constexpr int BK = 64;
static constexpr int STAGES = 3;
static constexpr int THREADS = 256;              // 8 warps: 4 (m) x 2 (n)
static constexpr int NCHUNK = DIN / BK;          // 64

static constexpr int A_STAGE_B = BM * BK * 2;    // 16384 B
static constexpr int B_STAGE_B = BN * BK * 2;    // 16384 B
static constexpr int STAGE_B   = A_STAGE_B + B_STAGE_B;   // 32768
static constexpr int SMEM_TOTAL = STAGES * STAGE_B;       // 98304 per CTA

// ---- scratch (device globals: allocation-free rule) ----
__device__ __half g_A [(size_t)TOKENS * DIN];    // 64 MB  (x as fp16)
__device__ __half g_Bs[(size_t)DOUT  * DIN];     // 128 MB (sign(w) as fp16)

// ============================ PTX helpers ===================================
__device__ __forceinline__ uint32_t smem_u32(const void* p) {
    uint32_t a;
    asm("{ .reg .u64 t; cvta.to.shared.u64 t, %1; cvt.u32.u64 %0, t; }"
        : "=r"(a) : "l"(p));
    return a;
}
__device__ __forceinline__ void cp_async16(uint32_t saddr, const void* gptr) {
    asm volatile("cp.async.cg.shared.global [%0], [%1], 16;"
                 :: "r"(saddr), "l"(gptr) : "memory");
}
__device__ __forceinline__ void cp_commit() {
    asm volatile("cp.async.commit_group;" ::: "memory");
}
template <int N>
__device__ __forceinline__ void cp_wait() {
    asm volatile("cp.async.wait_group %0;" :: "n"(N) : "memory");
}
__device__ __forceinline__ void ldmatrix_x4(uint32_t& r0, uint32_t& r1,
                                            uint32_t& r2, uint32_t& r3,
                                            uint32_t addr) {
    asm volatile("ldmatrix.sync.aligned.m8n8.x4.shared.b16 {%0,%1,%2,%3}, [%4];"
                 : "=r"(r0), "=r"(r1), "=r"(r2), "=r"(r3) : "r"(addr));
}
__device__ __forceinline__ void mma_16816(float* c, const uint32_t* a,
                                          const uint32_t* b) {
    asm volatile(
        "mma.sync.aligned.m16n8k16.row.col.f32.f16.f16.f32 "
        "{%0,%1,%2,%3}, {%4,%5,%6,%7}, {%8,%9}, {%0,%1,%2,%3};"
        : "+f"(c[0]), "+f"(c[1]), "+f"(c[2]), "+f"(c[3])
        : "r"(a[0]), "r"(a[1]), "r"(a[2]), "r"(a[3]), "r"(b[0]), "r"(b[1]));
}
// smem tile rows: BK fp16 = 128 B = 8 x 16B chunks; chunk' = chunk ^ (row&7)
__device__ __forceinline__ uint32_t sw_off(int row, int chunk) {
    return (uint32_t)((row << 7) + ((chunk ^ (row & 7)) << 4));
}

// ============================ prep kernels ==================================
__global__ void prep_a_kernel(const float* __restrict__ x) {
    size_t i = (size_t)blockIdx.x * blockDim.x + threadIdx.x;
    const size_t n4 = (size_t)TOKENS * DIN / 4;
    if (i >= n4) return;
    float4 v = __ldg((const float4*)x + i);
    uint32_t h0 = __half_as_ushort(__float2half_rn(v.x))
                | ((uint32_t)__half_as_ushort(__float2half_rn(v.y)) << 16);
    uint32_t h1 = __half_as_ushort(__float2half_rn(v.z))
                | ((uint32_t)__half_as_ushort(__float2half_rn(v.w)) << 16);
    uint2 p; p.x = h0; p.y = h1;
    ((uint2*)g_A)[i] = p;
}
__global__ void prep_b_kernel(const float* __restrict__ w) {
    size_t i = (size_t)blockIdx.x * blockDim.x + threadIdx.x;
    const size_t n4 = (size_t)DOUT * DIN / 4;
    if (i >= n4) return;
    float4 v = __ldg((const float4*)w + i);
    uint32_t s0 = (v.x >= 0.0f) ? 0x3C00u : 0xBC00u;
    uint32_t s1 = (v.y >= 0.0f) ? 0x3C00u : 0xBC00u;
    uint32_t s2 = (v.z >= 0.0f) ? 0x3C00u : 0xBC00u;
    uint32_t s3 = (v.w >= 0.0f) ? 0x3C00u : 0xBC00u;
    uint2 p; p.x = s0 | (s1 << 16); p.y = s2 | (s3 << 16);
    ((uint2*)g_Bs)[i] = p;
}

// ============================ GEMM kernel ===================================
__global__ void __launch_bounds__(THREADS, 2)
qat_gemm_kernel(const float* __restrict__ scale, const float* __restrict__ bias,
                float* __restrict__ out) {
    extern __shared__ char smem[];
    const uint32_t sbase = smem_u32(smem);
    const int tid  = threadIdx.x;
    const int wid  = tid >> 5;
    const int lane = tid & 31;

    // grouped tile swizzle (GROUP_M = 8): 64 m-tiles x 128 n-tiles
    const int pid   = blockIdx.x;                 // 0 .. 8191
    const int group = pid >> 10;                  // / (8*128)
    const int inb   = pid & 1023;
    const int pid_m = (group << 3) + (inb & 7);
    const int pid_n = inb >> 3;
    const int m0 = pid_m * BM;
    const int n0 = pid_n * BN;

    // phase stagger: wave partners (pid, pid+148) anti-align their k-loops
    const int coff = ((pid / 148) & 1) ? (NCHUNK / 2) : 0;

    // warp tile: 32 (m) x 64 (n); warps: 4 (m) x 2 (n)
    const int warp_m = wid & 3;
    const int warp_n = wid >> 2;
    const int wm0 = warp_m * 32;
    const int wn0 = warp_n * 64;

    // ---- global load indices (16B per cp.async; rows are 8x16B chunks) ----
    const int g_row = tid >> 3;               // 0..31
    const int g_chk = tid & 7;

    const __half* gA0 = g_A  + (size_t)(m0 + g_row) * DIN + g_chk * 8;
    const __half* gA1 = gA0 + (size_t)32 * DIN;
    const __half* gA2 = gA0 + (size_t)64 * DIN;
    const __half* gA3 = gA0 + (size_t)96 * DIN;
    const __half* gB0 = g_Bs + (size_t)(n0 + g_row) * DIN + g_chk * 8;
    const __half* gB1 = gB0 + (size_t)32 * DIN;
    const __half* gB2 = gB0 + (size_t)64 * DIN;
    const __half* gB3 = gB0 + (size_t)96 * DIN;

    const uint32_t sO0 = sw_off(g_row,      g_chk);
    const uint32_t sO1 = sw_off(g_row + 32, g_chk);
    const uint32_t sO2 = sw_off(g_row + 64, g_chk);
    const uint32_t sO3 = sw_off(g_row + 96, g_chk);

    // cc = pipeline position (stage slot = cc % STAGES); gmem chunk = rotated
    auto issue_stage = [&](int cc) {
        const int s = cc % STAGES;
        const int c = (cc + coff) & (NCHUNK - 1);
        const uint32_t stA = sbase + s * STAGE_B;
        const uint32_t stB = stA + A_STAGE_B;
        const size_t kofs = (size_t)c * BK;
        cp_async16(stA + sO0, gA0 + kofs);
        cp_async16(stA + sO1, gA1 + kofs);
        cp_async16(stA + sO2, gA2 + kofs);
        cp_async16(stA + sO3, gA3 + kofs);
        cp_async16(stB + sO0, gB0 + kofs);
        cp_async16(stB + sO1, gB1 + kofs);
        cp_async16(stB + sO2, gB2 + kofs);
        cp_async16(stB + sO3, gB3 + kofs);
    };

    // ---- prologue: fill STAGES-1 stages ----
#pragma unroll
    for (int cc = 0; cc < STAGES - 1; ++cc) { issue_stage(cc); cp_commit(); }

    // ---- accumulators: 2 m-frags x 8 n-frags x 4 ----
    float acc[2][8][4];
#pragma unroll
    for (int i = 0; i < 2; ++i)
#pragma unroll
        for (int j = 0; j < 8; ++j)
#pragma unroll
            for (int q = 0; q < 4; ++q) acc[i][j][q] = 0.0f;

    const int lquad = lane >> 3;              // 0..3 : which 8x8 matrix
    const int lrow  = lane & 7;

#pragma unroll 1
    for (int cc = 0; cc < NCHUNK; ++cc) {
        cp_wait<STAGES - 2>();
        __syncthreads();   // single barrier: all warps done reading slot cc-1

        if (cc + STAGES - 1 < NCHUNK) issue_stage(cc + STAGES - 1);
        cp_commit();

        const int s = cc % STAGES;
        const uint32_t stA = sbase + s * STAGE_B;
        const uint32_t stB = stA + A_STAGE_B;

#pragma unroll
        for (int kh = 0; kh < 4; ++kh) {      // four k16 halves of BK=64
            const int kchunk = kh * 2;        // 16B-chunk index of k16 base

            // A frags: 2 m16 tiles
            uint32_t afr[2][4];
#pragma unroll
            for (int mi = 0; mi < 2; ++mi) {
                int row = wm0 + mi * 16 + lrow + ((lquad & 1) << 3);
                int chk = kchunk + (lquad >> 1);
                ldmatrix_x4(afr[mi][0], afr[mi][1], afr[mi][2], afr[mi][3],
                            stA + sw_off(row, chk));
            }
            // B frags: 8 n8 tiles, 2 per ldmatrix.x4
            uint32_t bfr[8][2];
#pragma unroll
            for (int jp = 0; jp < 4; ++jp) {
                int row = wn0 + jp * 16 + lrow + ((lquad >> 1) << 3);
                int chk = kchunk + (lquad & 1);
                uint32_t r0, r1, r2, r3;
                ldmatrix_x4(r0, r1, r2, r3, stB + sw_off(row, chk));
                bfr[jp * 2 + 0][0] = r0; bfr[jp * 2 + 0][1] = r1;
                bfr[jp * 2 + 1][0] = r2; bfr[jp * 2 + 1][1] = r3;
            }
#pragma unroll
            for (int mi = 0; mi < 2; ++mi)
#pragma unroll
                for (int j = 0; j < 8; ++j)
                    mma_16816(acc[mi][j], afr[mi], bfr[j]);
        }
    }

    // ---- epilogue: fused scale/bias, float2 stores ----
    const int tq = lane >> 2;                 // 0..7 (row within frag)
    const int tr = lane & 3;                  // col pair selector
#pragma unroll
    for (int j = 0; j < 8; ++j) {
        const int n = n0 + wn0 + j * 8 + 2 * tr;
        const float2 sc = *(const float2*)(scale + n);
        const float2 bb = *(const float2*)(bias + n);
#pragma unroll
        for (int mi = 0; mi < 2; ++mi) {
            const int mrow = m0 + wm0 + mi * 16 + tq;
            float2 v0, v1;
            v0.x = fmaf(sc.x, acc[mi][j][0], bb.x);
            v0.y = fmaf(sc.y, acc[mi][j][1], bb.y);
            v1.x = fmaf(sc.x, acc[mi][j][2], bb.x);
            v1.y = fmaf(sc.y, acc[mi][j][3], bb.y);
            *(float2*)(out + (size_t)mrow * DOUT + n) = v0;
            *(float2*)(out + (size_t)(mrow + 8) * DOUT + n) = v1;
        }
    }
}

// ============================ launch ========================================
extern "C" void kernel_launch(void* const* d_in, const int* in_sizes, int n_in,
                              void* d_out, int out_size) {
    (void)in_sizes; (void)n_in; (void)out_size;
    const float* x     = (const float*)d_in[0];
    const float* w     = (const float*)d_in[1];
    const float* scale = (const float*)d_in[2];
    const float* b     = (const float*)d_in[3];
    float* out = (float*)d_out;

    {
        size_t n4 = (size_t)TOKENS * DIN / 4;
        prep_a_kernel<<<(unsigned)((n4 + 255) / 256), 256>>>(x);
    }
    {
        size_t n4 = (size_t)DOUT * DIN / 4;
        prep_b_kernel<<<(unsigned)((n4 + 255) / 256), 256>>>(w);
    }

    cudaFuncSetAttribute(qat_gemm_kernel,
                         cudaFuncAttributeMaxDynamicSharedMemorySize,
                         SMEM_TOTAL);
    const int grid = (TOKENS / BM) * (DOUT / BN);   // 64 * 128 = 8192
    qat_gemm_kernel<<<grid, THREADS, SMEM_TOTAL>>>(scale, b, out);
}